// round 14
// baseline (speedup 1.0000x reference)
#include <cuda_runtime.h>
#include <cuda_fp16.h>
#include <cstdint>

#define N_NODES 100000
#define N_EDGES 300000
#define IN_CH   256
#define NCOLS   512

// Scratch (__device__ globals; no allocs allowed)
__device__ __half   g_C[(size_t)N_NODES * NCOLS];    // scaled layer-1 pre-act, fp16 (102.4 MB)
__device__ __half   g_Bt[NCOLS * IN_CH];             // fp16 rearranged W1 scaled by |W2[h]|
__device__ float    g_b1s[IN_CH];                    // |W2[h]| * b1[h]
__device__ uint32_t g_sgnh[IN_CH / 2];               // half2(+-1, +-1) = sign(W2) pairs

__device__ __forceinline__ uint32_t smem_u32(const void* p) {
    uint32_t a;
    asm("{ .reg .u64 t; cvta.to.shared.u64 t, %1; cvt.u32.u64 %0, t; }" : "=r"(a) : "l"(p));
    return a;
}

// ---------------------------------------------------------------------------
// Prep B: g_Bt[n][k] = fp16( (n<256 ? W1[n][k] : W1[n-256][256+k]) * |W2[n&255]| )
// Also: g_b1s[h] = |W2[h]|*b1[h];  g_sgnh = half2 sign(+-1) pairs of W2.
// ---------------------------------------------------------------------------
__global__ void prep_b_kernel(const float* __restrict__ W1,
                              const float* __restrict__ W2,
                              const float* __restrict__ b1) {
    int idx = blockIdx.x * blockDim.x + threadIdx.x;
    if (idx < NCOLS * IN_CH) {
        int n = idx >> 8;
        int k = idx & 255;
        int h = n & 255;
        float w = W1[h * 512 + (n >> 8) * 256 + k] * fabsf(W2[h]);
        g_Bt[idx] = __float2half(w);
    }
    if (idx < IN_CH) g_b1s[idx] = fabsf(W2[idx]) * b1[idx];
    if (idx < IN_CH / 2) {
        float s0 = (W2[2 * idx]     < 0.f) ? -1.f : 1.f;
        float s1 = (W2[2 * idx + 1] < 0.f) ? -1.f : 1.f;
        union { __half2 h; uint32_t u; } v;
        v.h = __floats2half2_rn(s0, s1);
        g_sgnh[idx] = v.u;
    }
}

// ---------------------------------------------------------------------------
// fp16 mma.sync GEMM — R11 3-stage cp.async ring, but with the producer-side
// A work (STS of next chunk + LDG of chunk after) INTERLEAVED into the MMA
// body (one quarter per k16 step) so the tensor pipe never idles on it.
// g_C[M,512] = fp16( fp16(z[M,256]) @ g_Bt[512,256]^T ) (+ bias on dst half)
// CTA tile 128x256, BKH=64 halves, 256 threads = 8 warps (2x4), warp 64x64.
// ---------------------------------------------------------------------------
#define BM 128
#define BN 256
#define BKH 64                      // K halves per chunk (= 32 u32 words)
#define LDW 36                      // row stride in u32 words (32 + 4 pad)
#define KTILES (IN_CH / BKH)        // 4 chunks
#define A_W (BM * LDW)              // 4608 words (fp16 A tile region)
#define B_W (BN * LDW)              // 9216 words
#define STAGE_W (A_W + B_W)         // 13824 words = 55296 B
#define NSTAGE 3
#define SMEM_BYTES (NSTAGE * STAGE_W * 4)   // 165888

#define CP_ASYNC(dst, src, sz) \
    asm volatile("cp.async.ca.shared.global [%0], [%1], 16, %2;" \
                 :: "r"(dst), "l"(src), "r"(sz))
#define CP_COMMIT()  asm volatile("cp.async.commit_group;" ::: "memory")
#define CP_WAIT2()   asm volatile("cp.async.wait_group 2;" ::: "memory")

__global__ __launch_bounds__(256, 1) void gemm_fused_kernel(const float* __restrict__ z) {
    extern __shared__ uint32_t smw[];
    const uint32_t sb = smem_u32(smw);

    const int tid  = threadIdx.x;
    const int wid  = tid >> 5;
    const int lane = tid & 31;
    const int g = lane >> 2;            // 0..7
    const int t = lane & 3;             // 0..3
    const int wm = (wid & 1) * 64;
    const int wn = (wid >> 1) * 64;

    const int m0 = blockIdx.y * BM;
    const int n0 = blockIdx.x * BN;

    const uint32_t a_lm_word = (uint32_t)((wm + (lane & 15)) * LDW + (lane >> 4) * 4);

    float4 a_pre[8];

    float c[4][8][4];
    #pragma unroll
    for (int i = 0; i < 4; i++)
        #pragma unroll
        for (int j = 0; j < 8; j++)
            #pragma unroll
            for (int r = 0; r < 4; r++)
                c[i][j][r] = 0.f;

    auto ldgA = [&](int kt) {
        #pragma unroll
        for (int i = 0; i < 8; i++) {
            int idx = tid + i * 256;
            int row = idx >> 4;
            int c4  = idx & 15;
            int grow = m0 + row;
            a_pre[i] = (grow < N_NODES)
                ? *(const float4*)(z + (size_t)grow * IN_CH + kt * BKH + c4 * 4)
                : make_float4(0.f, 0.f, 0.f, 0.f);
        }
    };
    auto stsA = [&](int buf) {
        const uint32_t abase = sb + (uint32_t)(buf * STAGE_W) * 4;
        #pragma unroll
        for (int i = 0; i < 8; i++) {
            int idx = tid + i * 256;
            int row = idx >> 4;
            int c4  = idx & 15;
            union { __half2 h[2]; uint2 u; } v;
            v.h[0] = __floats2half2_rn(a_pre[i].x, a_pre[i].y);
            v.h[1] = __floats2half2_rn(a_pre[i].z, a_pre[i].w);
            uint32_t dst = abase + (uint32_t)(row * LDW + c4 * 2) * 4;
            asm volatile("st.shared.v2.b32 [%0], {%1, %2};"
                         :: "r"(dst), "r"(v.u.x), "r"(v.u.y) : "memory");
        }
    };
    auto issueB = [&](int buf, int kt) {
        const uint32_t bbase = sb + (uint32_t)(buf * STAGE_W + A_W) * 4;
        #pragma unroll
        for (int i = 0; i < 8; i++) {
            int idx = tid + i * 256;
            int row = idx >> 3;
            int c16 = idx & 7;
            const __half* src = g_Bt + (size_t)(n0 + row) * IN_CH + kt * BKH + c16 * 8;
            uint32_t dst = bbase + (uint32_t)(row * LDW + c16 * 4) * 4;
            CP_ASYNC(dst, src, 16);
        }
    };

    // MMA on chunk buf with interleaved producer quarters (next-chunk STS,
    // chunk-after LDG). a_pre[i]: STS'd (old value) then reloaded (new value)
    // in the same quarter — register dependency keeps the order.
    auto mma_chunk_fused = [&](int buf, bool do_sts, int nbuf, bool do_ldg, int lkt) {
        const uint32_t abase = sb + (uint32_t)(buf * STAGE_W) * 4;
        const uint32_t* Bs = smw + buf * STAGE_W + A_W;
        const uint32_t a_lm_base = abase + a_lm_word * 4;
        const uint32_t nabase = sb + (uint32_t)(nbuf * STAGE_W) * 4;
        #pragma unroll
        for (int s = 0; s < 4; s++) {
            // Producer quarter: a_pre elements 2s, 2s+1
            #pragma unroll
            for (int q = 0; q < 2; q++) {
                const int i = s * 2 + q;
                const int idx = tid + i * 256;
                const int row = idx >> 4;
                const int c4  = idx & 15;
                if (do_sts) {
                    union { __half2 h[2]; uint2 u; } v;
                    v.h[0] = __floats2half2_rn(a_pre[i].x, a_pre[i].y);
                    v.h[1] = __floats2half2_rn(a_pre[i].z, a_pre[i].w);
                    uint32_t dst = nabase + (uint32_t)(row * LDW + c4 * 2) * 4;
                    asm volatile("st.shared.v2.b32 [%0], {%1, %2};"
                                 :: "r"(dst), "r"(v.u.x), "r"(v.u.y) : "memory");
                }
                if (do_ldg) {
                    int grow = m0 + row;
                    a_pre[i] = (grow < N_NODES)
                        ? *(const float4*)(z + (size_t)grow * IN_CH + lkt * BKH + c4 * 4)
                        : make_float4(0.f, 0.f, 0.f, 0.f);
                }
            }
            const int kb = s * 8;
            uint32_t bfr[8][2];
            #pragma unroll
            for (int nf = 0; nf < 8; nf++) {
                const int br = wn + nf * 8 + g;
                bfr[nf][0] = Bs[br * LDW + kb + t];
                bfr[nf][1] = Bs[br * LDW + kb + t + 4];
            }
            #pragma unroll
            for (int mf = 0; mf < 4; mf++) {
                uint32_t a0, a1, a2, a3;
                uint32_t aaddr = a_lm_base + (uint32_t)(mf * 16 * LDW + kb) * 4;
                asm volatile(
                    "ldmatrix.sync.aligned.m8n8.x4.shared.b16 {%0,%1,%2,%3}, [%4];"
                    : "=r"(a0), "=r"(a1), "=r"(a2), "=r"(a3) : "r"(aaddr));
                #pragma unroll
                for (int nf = 0; nf < 8; nf++) {
                    asm volatile(
                        "mma.sync.aligned.m16n8k16.row.col.f32.f16.f16.f32 "
                        "{%0,%1,%2,%3}, {%4,%5,%6,%7}, {%8,%9}, {%0,%1,%2,%3};"
                        : "+f"(c[mf][nf][0]), "+f"(c[mf][nf][1]),
                          "+f"(c[mf][nf][2]), "+f"(c[mf][nf][3])
                        : "r"(a0), "r"(a1), "r"(a2), "r"(a3),
                          "r"(bfr[nf][0]), "r"(bfr[nf][1]));
                }
            }
        }
    };

    // Prologue
    ldgA(0);
    issueB(0, 0); CP_COMMIT();
    issueB(1, 1); CP_COMMIT();
    issueB(2, 2); CP_COMMIT();
    stsA(0);                 // startup only
    ldgA(1);

    for (int kt = 0; kt < KTILES; kt++) {
        const int buf = kt % NSTAGE;
        CP_WAIT2();
        __syncthreads();

        const bool do_sts = (kt + 1 < KTILES);
        const bool do_ldg = (kt + 2 < KTILES);
        mma_chunk_fused(buf, do_sts, (kt + 1) % NSTAGE, do_ldg, kt + 2);

        __syncthreads();
        if (kt + NSTAGE < KTILES) issueB((kt + NSTAGE) % NSTAGE, kt + NSTAGE);
        CP_COMMIT();
    }

    // Epilogue: add scaled bias on dst half, convert to fp16
    const bool dsthalf = (n0 >= 256);
    #pragma unroll
    for (int mf = 0; mf < 4; mf++) {
        const int row_a = m0 + wm + mf * 16 + g;
        const int row_b = row_a + 8;
        #pragma unroll
        for (int nf = 0; nf < 8; nf++) {
            const int colh = wn + nf * 8 + t * 2;
            float bx = 0.f, by = 0.f;
            if (dsthalf) { bx = g_b1s[colh]; by = g_b1s[colh + 1]; }
            const int col = n0 + colh;
            if (row_a < N_NODES)
                *(__half2*)&g_C[(size_t)row_a * NCOLS + col] =
                    __floats2half2_rn(c[mf][nf][0] + bx, c[mf][nf][1] + by);
            if (row_b < N_NODES)
                *(__half2*)&g_C[(size_t)row_b * NCOLS + col] =
                    __floats2half2_rn(c[mf][nf][2] + bx, c[mf][nf][3] + by);
        }
    }
}

// ---------------------------------------------------------------------------
// Edge kernel: TWO edges per warp, half2 math (hadd2/hmax2/hmul2 + fp32 accum).
// out[e] = b2 + sum_h sign(W2[h]) * relu(Cs[src][h] + Cd[dst][h])
// ---------------------------------------------------------------------------
__global__ __launch_bounds__(256) void edge_kernel(
    const int* __restrict__ ei,
    const float* __restrict__ b2,
    float* __restrict__ out)
{
    int warp = (blockIdx.x * blockDim.x + threadIdx.x) >> 5;
    int lane = threadIdx.x & 31;
    int half = lane >> 4;
    int sl   = lane & 15;

    int e = warp * 2 + half;
    if (e >= N_EDGES) return;

    int s = ei[e];
    int d = ei[N_EDGES + e];

    const __half* arow = &g_C[(size_t)s * NCOLS] + sl * 16;
    const __half* brow = &g_C[(size_t)d * NCOLS + IN_CH] + sl * 16;

    union U4 { uint4 u; __half2 h[4]; };
    U4 ua0, ua1, ub0, ub1, sg0, sg1;
    ua0.u = *(const uint4*)(arow);
    ua1.u = *(const uint4*)(arow + 8);
    ub0.u = *(const uint4*)(brow);
    ub1.u = *(const uint4*)(brow + 8);
    sg0.u = *(const uint4*)(&g_sgnh[sl * 8]);
    sg1.u = *(const uint4*)(&g_sgnh[sl * 8 + 4]);

    const __half2 z2 = __float2half2_rn(0.f);
    float sum = 0.f;
    #pragma unroll
    for (int i = 0; i < 4; i++) {
        __half2 r = __hmul2(__hmax2(__hadd2(ua0.h[i], ub0.h[i]), z2), sg0.h[i]);
        float2 f = __half22float2(r);
        sum += f.x + f.y;
    }
    #pragma unroll
    for (int i = 0; i < 4; i++) {
        __half2 r = __hmul2(__hmax2(__hadd2(ua1.h[i], ub1.h[i]), z2), sg1.h[i]);
        float2 f = __half22float2(r);
        sum += f.x + f.y;
    }

    #pragma unroll
    for (int o = 8; o; o >>= 1)
        sum += __shfl_xor_sync(0xFFFFFFFFu, sum, o);

    if (sl == 0)
        out[e] = sum + b2[0];
}

// ---------------------------------------------------------------------------
extern "C" void kernel_launch(void* const* d_in, const int* in_sizes, int n_in,
                              void* d_out, int out_size)
{
    const float* z   = (const float*)d_in[0];
    const float* W1  = (const float*)d_in[1];
    const float* b1  = (const float*)d_in[2];
    const float* W2  = (const float*)d_in[3];
    const float* b2  = (const float*)d_in[4];
    const int*   ei  = (const int*)d_in[5];
    float*       out = (float*)d_out;

    cudaFuncSetAttribute(gemm_fused_kernel,
                         cudaFuncAttributeMaxDynamicSharedMemorySize, SMEM_BYTES);

    prep_b_kernel<<<(NCOLS * IN_CH + 255) / 256, 256>>>(W1, W2, b1);

    dim3 grid(NCOLS / BN, (N_NODES + BM - 1) / BM);   // (2, 782)
    gemm_fused_kernel<<<grid, 256, SMEM_BYTES>>>(z);

    int edge_blocks = (N_EDGES / 2 + 7) / 8;   // 8 warps/block, 2 edges/warp
    edge_kernel<<<edge_blocks, 256>>>(ei, b2, out);
}

// round 15
// speedup vs baseline: 1.3482x; 1.3482x over previous
#include <cuda_runtime.h>
#include <cuda_fp16.h>
#include <cstdint>

#define N_NODES 100000
#define N_EDGES 300000
#define IN_CH   256
#define NCOLS   512

// Scratch (__device__ globals; no allocs allowed)
__device__ __half   g_C[(size_t)N_NODES * NCOLS];    // scaled layer-1 pre-act, fp16 (102.4 MB)
__device__ __half   g_Bt[NCOLS * IN_CH];             // fp16 rearranged W1 scaled by |W2[h]|
__device__ float    g_b1s[IN_CH];                    // |W2[h]| * b1[h]
__device__ uint32_t g_sgnh[IN_CH / 2];               // half2(+-1, +-1) = sign(W2) pairs

__device__ __forceinline__ uint32_t smem_u32(const void* p) {
    uint32_t a;
    asm("{ .reg .u64 t; cvta.to.shared.u64 t, %1; cvt.u32.u64 %0, t; }" : "=r"(a) : "l"(p));
    return a;
}

// ---------------------------------------------------------------------------
// Prep B: g_Bt[n][k] = fp16( (n<256 ? W1[n][k] : W1[n-256][256+k]) * |W2[n&255]| )
// Also: g_b1s[h] = |W2[h]|*b1[h];  g_sgnh = half2 sign(+-1) pairs of W2.
// ---------------------------------------------------------------------------
__global__ void prep_b_kernel(const float* __restrict__ W1,
                              const float* __restrict__ W2,
                              const float* __restrict__ b1) {
    int idx = blockIdx.x * blockDim.x + threadIdx.x;
    if (idx < NCOLS * IN_CH) {
        int n = idx >> 8;
        int k = idx & 255;
        int h = n & 255;
        float w = W1[h * 512 + (n >> 8) * 256 + k] * fabsf(W2[h]);
        g_Bt[idx] = __float2half(w);
    }
    if (idx < IN_CH) g_b1s[idx] = fabsf(W2[idx]) * b1[idx];
    if (idx < IN_CH / 2) {
        float s0 = (W2[2 * idx]     < 0.f) ? -1.f : 1.f;
        float s1 = (W2[2 * idx + 1] < 0.f) ? -1.f : 1.f;
        union { __half2 h; uint32_t u; } v;
        v.h = __floats2half2_rn(s0, s1);
        g_sgnh[idx] = v.u;
    }
}

// ---------------------------------------------------------------------------
// fp16 mma.sync GEMM — EXACT R13 champion (3-stage cp.async ring, fused
// producer-side A conversion, phase-separated producer/MMA). DO NOT TOUCH.
// g_C[M,512] = fp16( fp16(z[M,256]) @ g_Bt[512,256]^T ) (+ bias on dst half)
// CTA tile 128x256, BKH=64 halves, 256 threads = 8 warps (2x4), warp 64x64.
// ---------------------------------------------------------------------------
#define BM 128
#define BN 256
#define BKH 64                      // K halves per chunk (= 32 u32 words)
#define LDW 36                      // row stride in u32 words (32 + 4 pad)
#define KTILES (IN_CH / BKH)        // 4 chunks
#define A_W (BM * LDW)              // 4608 words (fp16 A tile region)
#define B_W (BN * LDW)              // 9216 words
#define STAGE_W (A_W + B_W)         // 13824 words = 55296 B
#define NSTAGE 3
#define SMEM_BYTES (NSTAGE * STAGE_W * 4)   // 165888

#define CP_ASYNC(dst, src, sz) \
    asm volatile("cp.async.ca.shared.global [%0], [%1], 16, %2;" \
                 :: "r"(dst), "l"(src), "r"(sz))
#define CP_COMMIT()  asm volatile("cp.async.commit_group;" ::: "memory")
#define CP_WAIT2()   asm volatile("cp.async.wait_group 2;" ::: "memory")

__global__ __launch_bounds__(256, 1) void gemm_fused_kernel(const float* __restrict__ z) {
    extern __shared__ uint32_t smw[];
    const uint32_t sb = smem_u32(smw);

    const int tid  = threadIdx.x;
    const int wid  = tid >> 5;
    const int lane = tid & 31;
    const int g = lane >> 2;            // 0..7
    const int t = lane & 3;             // 0..3
    const int wm = (wid & 1) * 64;
    const int wn = (wid >> 1) * 64;

    const int m0 = blockIdx.y * BM;
    const int n0 = blockIdx.x * BN;

    const uint32_t a_lm_word = (uint32_t)((wm + (lane & 15)) * LDW + (lane >> 4) * 4);

    float4 a_pre[8];

    float c[4][8][4];
    #pragma unroll
    for (int i = 0; i < 4; i++)
        #pragma unroll
        for (int j = 0; j < 8; j++)
            #pragma unroll
            for (int r = 0; r < 4; r++)
                c[i][j][r] = 0.f;

    auto ldgA = [&](int kt) {
        #pragma unroll
        for (int i = 0; i < 8; i++) {
            int idx = tid + i * 256;
            int row = idx >> 4;
            int c4  = idx & 15;
            int grow = m0 + row;
            a_pre[i] = (grow < N_NODES)
                ? *(const float4*)(z + (size_t)grow * IN_CH + kt * BKH + c4 * 4)
                : make_float4(0.f, 0.f, 0.f, 0.f);
        }
    };
    auto stsA = [&](int buf) {
        const uint32_t abase = sb + (uint32_t)(buf * STAGE_W) * 4;
        #pragma unroll
        for (int i = 0; i < 8; i++) {
            int idx = tid + i * 256;
            int row = idx >> 4;
            int c4  = idx & 15;
            union { __half2 h[2]; uint2 u; } v;
            v.h[0] = __floats2half2_rn(a_pre[i].x, a_pre[i].y);
            v.h[1] = __floats2half2_rn(a_pre[i].z, a_pre[i].w);
            uint32_t dst = abase + (uint32_t)(row * LDW + c4 * 2) * 4;
            asm volatile("st.shared.v2.b32 [%0], {%1, %2};"
                         :: "r"(dst), "r"(v.u.x), "r"(v.u.y) : "memory");
        }
    };
    auto issueB = [&](int buf, int kt) {
        const uint32_t bbase = sb + (uint32_t)(buf * STAGE_W + A_W) * 4;
        #pragma unroll
        for (int i = 0; i < 8; i++) {
            int idx = tid + i * 256;
            int row = idx >> 3;
            int c16 = idx & 7;
            const __half* src = g_Bt + (size_t)(n0 + row) * IN_CH + kt * BKH + c16 * 8;
            uint32_t dst = bbase + (uint32_t)(row * LDW + c16 * 4) * 4;
            CP_ASYNC(dst, src, 16);
        }
    };

    // Prologue
    ldgA(0);
    issueB(0, 0); CP_COMMIT();
    issueB(1, 1); CP_COMMIT();
    issueB(2, 2); CP_COMMIT();
    stsA(0);                 // startup only
    ldgA(1);

    for (int kt = 0; kt < KTILES; kt++) {
        const int buf = kt % NSTAGE;
        CP_WAIT2();
        __syncthreads();

        if (kt + 1 < KTILES) {
            stsA((kt + 1) % NSTAGE);
            if (kt + 2 < KTILES) ldgA(kt + 2);
        }

        const uint32_t abase = sb + (uint32_t)(buf * STAGE_W) * 4;
        const uint32_t* Bs = smw + buf * STAGE_W + A_W;
        const uint32_t a_lm_base = abase + a_lm_word * 4;

        #pragma unroll
        for (int s = 0; s < 4; s++) {
            const int kb = s * 8;
            uint32_t bfr[8][2];
            #pragma unroll
            for (int nf = 0; nf < 8; nf++) {
                const int br = wn + nf * 8 + g;
                bfr[nf][0] = Bs[br * LDW + kb + t];
                bfr[nf][1] = Bs[br * LDW + kb + t + 4];
            }
            #pragma unroll
            for (int mf = 0; mf < 4; mf++) {
                uint32_t a0, a1, a2, a3;
                uint32_t aaddr = a_lm_base + (uint32_t)(mf * 16 * LDW + kb) * 4;
                asm volatile(
                    "ldmatrix.sync.aligned.m8n8.x4.shared.b16 {%0,%1,%2,%3}, [%4];"
                    : "=r"(a0), "=r"(a1), "=r"(a2), "=r"(a3) : "r"(aaddr));
                #pragma unroll
                for (int nf = 0; nf < 8; nf++) {
                    asm volatile(
                        "mma.sync.aligned.m16n8k16.row.col.f32.f16.f16.f32 "
                        "{%0,%1,%2,%3}, {%4,%5,%6,%7}, {%8,%9}, {%0,%1,%2,%3};"
                        : "+f"(c[mf][nf][0]), "+f"(c[mf][nf][1]),
                          "+f"(c[mf][nf][2]), "+f"(c[mf][nf][3])
                        : "r"(a0), "r"(a1), "r"(a2), "r"(a3),
                          "r"(bfr[nf][0]), "r"(bfr[nf][1]));
                }
            }
        }
        __syncthreads();
        if (kt + NSTAGE < KTILES) issueB((kt + NSTAGE) % NSTAGE, kt + NSTAGE);
        CP_COMMIT();
    }

    // Epilogue: add scaled bias on dst half, convert to fp16
    const bool dsthalf = (n0 >= 256);
    #pragma unroll
    for (int mf = 0; mf < 4; mf++) {
        const int row_a = m0 + wm + mf * 16 + g;
        const int row_b = row_a + 8;
        #pragma unroll
        for (int nf = 0; nf < 8; nf++) {
            const int colh = wn + nf * 8 + t * 2;
            float bx = 0.f, by = 0.f;
            if (dsthalf) { bx = g_b1s[colh]; by = g_b1s[colh + 1]; }
            const int col = n0 + colh;
            if (row_a < N_NODES)
                *(__half2*)&g_C[(size_t)row_a * NCOLS + col] =
                    __floats2half2_rn(c[mf][nf][0] + bx, c[mf][nf][1] + by);
            if (row_b < N_NODES)
                *(__half2*)&g_C[(size_t)row_b * NCOLS + col] =
                    __floats2half2_rn(c[mf][nf][2] + bx, c[mf][nf][3] + by);
        }
    }
}

// ---------------------------------------------------------------------------
// Edge kernel: FOUR edges per warp — each 16-lane group handles 2 edges
// sequentially with ALL 8 gather loads issued up front (2x MLP vs R13).
// Same 16-lane/16B-per-lane gather shape as the proven R8/R13 kernels.
// out[e] = b2 + sum_h sign(W2[h]) * relu(Cs[src][h] + Cd[dst][h])
// ---------------------------------------------------------------------------
__global__ __launch_bounds__(256) void edge_kernel(
    const int* __restrict__ ei,
    const float* __restrict__ b2,
    float* __restrict__ out)
{
    int warp = (blockIdx.x * blockDim.x + threadIdx.x) >> 5;
    int lane = threadIdx.x & 31;
    int half = lane >> 4;               // 16-lane group id
    int sl   = lane & 15;               // sub-lane

    int e0 = warp * 4 + half * 2;       // this group's first edge
    if (e0 >= N_EDGES) return;
    int e1 = e0 + 1;                    // N_EDGES divisible by 4: always valid

    int s0 = ei[e0], d0 = ei[N_EDGES + e0];
    int s1 = ei[e1], d1 = ei[N_EDGES + e1];

    const __half* a0p = &g_C[(size_t)s0 * NCOLS] + sl * 16;
    const __half* b0p = &g_C[(size_t)d0 * NCOLS + IN_CH] + sl * 16;
    const __half* a1p = &g_C[(size_t)s1 * NCOLS] + sl * 16;
    const __half* b1p = &g_C[(size_t)d1 * NCOLS + IN_CH] + sl * 16;

    union U4 { uint4 u; __half2 h[4]; };
    // Issue all 8 gathers up front (2x MLP)
    U4 xa0, xa1, xb0, xb1, ya0, ya1, yb0, yb1, sg0, sg1;
    xa0.u = *(const uint4*)(a0p);
    xa1.u = *(const uint4*)(a0p + 8);
    xb0.u = *(const uint4*)(b0p);
    xb1.u = *(const uint4*)(b0p + 8);
    ya0.u = *(const uint4*)(a1p);
    ya1.u = *(const uint4*)(a1p + 8);
    yb0.u = *(const uint4*)(b1p);
    yb1.u = *(const uint4*)(b1p + 8);
    sg0.u = *(const uint4*)(&g_sgnh[sl * 8]);
    sg1.u = *(const uint4*)(&g_sgnh[sl * 8 + 4]);

    const __half2 z2 = __float2half2_rn(0.f);
    float sum0 = 0.f, sum1 = 0.f;
    #pragma unroll
    for (int i = 0; i < 4; i++) {
        __half2 r0 = __hmul2(__hmax2(__hadd2(xa0.h[i], xb0.h[i]), z2), sg0.h[i]);
        __half2 r1 = __hmul2(__hmax2(__hadd2(xa1.h[i], xb1.h[i]), z2), sg1.h[i]);
        float2 f0 = __half22float2(r0);
        float2 f1 = __half22float2(r1);
        sum0 += (f0.x + f0.y) + (f1.x + f1.y);
        __half2 q0 = __hmul2(__hmax2(__hadd2(ya0.h[i], yb0.h[i]), z2), sg0.h[i]);
        __half2 q1 = __hmul2(__hmax2(__hadd2(ya1.h[i], yb1.h[i]), z2), sg1.h[i]);
        float2 g0 = __half22float2(q0);
        float2 g1 = __half22float2(q1);
        sum1 += (g0.x + g0.y) + (g1.x + g1.y);
    }

    // Reduce both sums within each 16-lane group
    #pragma unroll
    for (int o = 8; o; o >>= 1) {
        sum0 += __shfl_xor_sync(0xFFFFFFFFu, sum0, o);
        sum1 += __shfl_xor_sync(0xFFFFFFFFu, sum1, o);
    }

    if (sl == 0) {
        float bias = b2[0];
        *(float2*)&out[e0] = make_float2(sum0 + bias, sum1 + bias);
    }
}

// ---------------------------------------------------------------------------
extern "C" void kernel_launch(void* const* d_in, const int* in_sizes, int n_in,
                              void* d_out, int out_size)
{
    const float* z   = (const float*)d_in[0];
    const float* W1  = (const float*)d_in[1];
    const float* b1  = (const float*)d_in[2];
    const float* W2  = (const float*)d_in[3];
    const float* b2  = (const float*)d_in[4];
    const int*   ei  = (const int*)d_in[5];
    float*       out = (float*)d_out;

    cudaFuncSetAttribute(gemm_fused_kernel,
                         cudaFuncAttributeMaxDynamicSharedMemorySize, SMEM_BYTES);

    prep_b_kernel<<<(NCOLS * IN_CH + 255) / 256, 256>>>(W1, W2, b1);

    dim3 grid(NCOLS / BN, (N_NODES + BM - 1) / BM);   // (2, 782)
    gemm_fused_kernel<<<grid, 256, SMEM_BYTES>>>(z);

    int edge_blocks = (N_EDGES / 4 + 7) / 8;   // 8 warps/block, 4 edges/warp
    edge_kernel<<<edge_blocks, 256>>>(ei, b2, out);
}